// round 11
// baseline (speedup 1.0000x reference)
#include <cuda_runtime.h>
#include <math.h>
#include <stdint.h>

#define TT 2048
#define DD 3584
#define NH 28
#define KH 4
#define HD 128
#define GQ 7

// scratch (static __device__ arrays: allocation-free)
__device__ float g_q[(size_t)NH * TT * HD];
__device__ float g_k[(size_t)KH * TT * HD];
__device__ float g_v[(size_t)KH * TT * HD];
__device__ float g_ctx[(size_t)TT * DD];

// ---------------------------------------------------------------------------
// TF32 helpers
// ---------------------------------------------------------------------------
__device__ __forceinline__ float tf32f(float x) {   // round-to-nearest tf32, as float
    uint32_t r;
    asm("cvt.rna.tf32.f32 %0, %1;" : "=r"(r) : "f"(x));
    return __uint_as_float(r);
}

__device__ __forceinline__ void split_tf32(float x, uint32_t& hi, uint32_t& lo) {
    uint32_t h;
    asm("cvt.rna.tf32.f32 %0, %1;" : "=r"(h) : "f"(x));
    hi = h;
    lo = __float_as_uint(x - __uint_as_float(h));
}

__device__ __forceinline__ float2 split2_tf32(float x) {  // {hi, lo} as floats
    uint32_t h;
    asm("cvt.rna.tf32.f32 %0, %1;" : "=r"(h) : "f"(x));
    float hf = __uint_as_float(h);
    return make_float2(hf, x - hf);
}

__device__ __forceinline__ void mma_tf32(float c[4],
                                         uint32_t a0, uint32_t a1, uint32_t a2, uint32_t a3,
                                         uint32_t b0, uint32_t b1)
{
    asm volatile(
        "mma.sync.aligned.m16n8k8.row.col.f32.tf32.tf32.f32 "
        "{%0,%1,%2,%3},{%4,%5,%6,%7},{%8,%9},{%0,%1,%2,%3};"
        : "+f"(c[0]), "+f"(c[1]), "+f"(c[2]), "+f"(c[3])
        : "r"(a0), "r"(a1), "r"(a2), "r"(a3), "r"(b0), "r"(b1));
}

// 3 MMAs: small cross terms first, then main
__device__ __forceinline__ void mma3_tf32(float c[4],
                                          const uint32_t ah[4], const uint32_t al[4],
                                          uint32_t b0h, uint32_t b1h,
                                          uint32_t b0l, uint32_t b1l)
{
    mma_tf32(c, al[0], al[1], al[2], al[3], b0h, b1h);
    mma_tf32(c, ah[0], ah[1], ah[2], ah[3], b0l, b1l);
    mma_tf32(c, ah[0], ah[1], ah[2], ah[3], b0h, b1h);
}

// ---------------------------------------------------------------------------
// 3xTF32 GEMM core with PRE-SPLIT B in shared memory.
// C[128 x 128] = X[128 x DD] * W[DD x 128](slice) (+ bias)
// Xs[row][36] fp32 (A split-on-use; bank (4r+c)%32 conflict-free).
// Ws2[k][132] float2{hi,lo}: B-frag LDS.64; float-stride 264 == 8 mod 32 ->
//   banks (8*tg + 2*g) distinct within each 16-lane phase -> conflict-free.
// ---------------------------------------------------------------------------
#define XS_STRIDE 36
#define WS2_STRIDE 132   // in float2 units

template<bool HAS_BIAS>
__device__ __forceinline__ void gemm_core_tf32(
    const float* __restrict__ Xbase,
    const float* __restrict__ Wbase, int ldw,
    const float* __restrict__ bias,
    float* __restrict__ Obase, int ldo)
{
    __shared__ float  Xs[128 * XS_STRIDE];
    __shared__ float2 Ws2[32 * WS2_STRIDE];

    int tid  = threadIdx.x;
    int warp = tid >> 5, lane = tid & 31;
    int wm = warp >> 1;        // 0..3 -> rows wm*32
    int wn = warp & 1;         // 0..1 -> cols wn*64
    int g  = lane >> 2;        // 0..7
    int tg = lane & 3;         // 0..3

    float C[2][8][4];
#pragma unroll
    for (int mt = 0; mt < 2; mt++)
#pragma unroll
        for (int nt = 0; nt < 8; nt++)
#pragma unroll
            for (int r = 0; r < 4; r++) C[mt][nt][r] = 0.f;

    for (int k0 = 0; k0 < DD; k0 += 32) {
        // stage X tile: 128 rows x 32 cols (fp32)
#pragma unroll
        for (int it = 0; it < 4; it++) {
            int l = tid + it * 256;
            int row = l >> 3, c4 = l & 7;
            float4 v = *(const float4*)(Xbase + (size_t)row * DD + k0 + c4 * 4);
            *(float4*)&Xs[row * XS_STRIDE + c4 * 4] = v;
        }
        // stage W tile pre-split: Ws2[kk][n] = {hi, lo}
#pragma unroll
        for (int it = 0; it < 4; it++) {
            int l = tid + it * 256;
            int kk = l >> 5, nq = l & 31;
            float4 v = *(const float4*)(Wbase + (size_t)(k0 + kk) * ldw + nq * 4);
            float2 s0 = split2_tf32(v.x), s1 = split2_tf32(v.y);
            float2 s2 = split2_tf32(v.z), s3 = split2_tf32(v.w);
            float* dst = (float*)&Ws2[kk * WS2_STRIDE + nq * 4];
            *(float4*)dst       = make_float4(s0.x, s0.y, s1.x, s1.y);
            *(float4*)(dst + 4) = make_float4(s2.x, s2.y, s3.x, s3.y);
        }
        __syncthreads();

#pragma unroll
        for (int kk0 = 0; kk0 < 32; kk0 += 8) {
            uint32_t Ah[2][4], Al[2][4];
#pragma unroll
            for (int mt = 0; mt < 2; mt++) {
                int rb = wm * 32 + mt * 16;
                split_tf32(Xs[(rb + g)     * XS_STRIDE + kk0 + tg],     Ah[mt][0], Al[mt][0]);
                split_tf32(Xs[(rb + g + 8) * XS_STRIDE + kk0 + tg],     Ah[mt][1], Al[mt][1]);
                split_tf32(Xs[(rb + g)     * XS_STRIDE + kk0 + tg + 4], Ah[mt][2], Al[mt][2]);
                split_tf32(Xs[(rb + g + 8) * XS_STRIDE + kk0 + tg + 4], Ah[mt][3], Al[mt][3]);
            }
#pragma unroll
            for (int nt = 0; nt < 8; nt++) {
                int nb = wn * 64 + nt * 8;
                float2 f0 = Ws2[(kk0 + tg)     * WS2_STRIDE + nb + g];
                float2 f1 = Ws2[(kk0 + tg + 4) * WS2_STRIDE + nb + g];
                uint32_t b0h = __float_as_uint(f0.x), b0l = __float_as_uint(f0.y);
                uint32_t b1h = __float_as_uint(f1.x), b1l = __float_as_uint(f1.y);
                mma3_tf32(C[0][nt], Ah[0], Al[0], b0h, b1h, b0l, b1l);
                mma3_tf32(C[1][nt], Ah[1], Al[1], b0h, b1h, b0l, b1l);
            }
        }
        __syncthreads();
    }

#pragma unroll
    for (int mt = 0; mt < 2; mt++) {
#pragma unroll
        for (int nt = 0; nt < 8; nt++) {
            int row0 = wm * 32 + mt * 16 + g;
            int col  = wn * 64 + nt * 8 + tg * 2;
            float b0v = HAS_BIAS ? bias[col]     : 0.f;
            float b1v = HAS_BIAS ? bias[col + 1] : 0.f;
            *(float2*)&Obase[(size_t)row0 * ldo + col] =
                make_float2(C[mt][nt][0] + b0v, C[mt][nt][1] + b1v);
            *(float2*)&Obase[(size_t)(row0 + 8) * ldo + col] =
                make_float2(C[mt][nt][2] + b0v, C[mt][nt][3] + b1v);
        }
    }
}

// ---------------------------------------------------------------------------
// QKV projection (3xTF32). grid (T/128, 36), block 256.
// ---------------------------------------------------------------------------
__global__ __launch_bounds__(256, 2) void qkv_proj_tf32_kernel(
    const float* __restrict__ x,
    const float* __restrict__ wq, const float* __restrict__ bq,
    const float* __restrict__ wk, const float* __restrict__ bk,
    const float* __restrict__ wv, const float* __restrict__ bv)
{
    int z = blockIdx.y;
    const float* w; const float* b; float* out;
    if (z < NH)           { w = wq + (size_t)z * DD * HD;        b = bq + z * HD;        out = g_q + (size_t)z * TT * HD; }
    else if (z < NH + KH) { int c = z - NH;      w = wk + (size_t)c * DD * HD; b = bk + c * HD; out = g_k + (size_t)c * TT * HD; }
    else                  { int c = z - NH - KH; w = wv + (size_t)c * DD * HD; b = bv + c * HD; out = g_v + (size_t)c * TT * HD; }

    int t0 = blockIdx.x * 128;
    gemm_core_tf32<true>(x + (size_t)t0 * DD, w, HD, b, out + (size_t)t0 * HD, HD);
}

// ---------------------------------------------------------------------------
// Output projection (3xTF32). grid (T/128, D/128), block 256.
// ---------------------------------------------------------------------------
__global__ __launch_bounds__(256, 2) void out_proj_tf32_kernel(
    const float* __restrict__ wo, float* __restrict__ out)
{
    int t0 = blockIdx.x * 128;
    int n0 = blockIdx.y * 128;
    gemm_core_tf32<false>(g_ctx + (size_t)t0 * DD, wo + n0, DD, nullptr,
                          out + (size_t)t0 * DD + n0, DD);
}

// ---------------------------------------------------------------------------
// RoPE in-place on g_q (with 1/sqrt(H) scale) and g_k. fp64 angle math.
// grid: (T, NH+KH), block 64
// ---------------------------------------------------------------------------
__global__ void rope_kernel(const int* __restrict__ positions)
{
    int t = blockIdx.x;
    int hidx = blockIdx.y;
    int i = threadIdx.x;  // 0..63

    float* base; float scale;
    if (hidx < NH) { base = g_q + ((size_t)hidx * TT + t) * HD; scale = 0.08838834764831845f; }
    else           { base = g_k + ((size_t)(hidx - NH) * TT + t) * HD; scale = 1.0f; }

    int pos = positions[t];
    double inv_freq = pow(1000000.0, -(double)(2 * i) / 128.0);
    double ang = (double)pos * inv_freq;
    double sd, cd;
    sincos(ang, &sd, &cd);
    float c = (float)cd, s = (float)sd;
    float x1 = base[i], x2 = base[i + 64];
    base[i]      = (x1 * c - x2 * s) * scale;
    base[i + 64] = (x2 * c + x1 * s) * scale;
}

// ---------------------------------------------------------------------------
// Flash attention. S = QK^T in 3xTF32 (K pre-split in smem), P.V in 1xTF32
// (P and V tf32-rounded once; positive-sum P keeps the error ~3e-4).
// grid (T/128, NH), block 256 = 8 warps; warp w owns q-rows [16w, 16w+16).
// smem floats: Qs 128*132 | Ks2 64*132*2 | VsH 64*136 | Ps 128*68  -> 200 KB.
// Bank audit: Qs/Ps A-frags (4g+tg)%32 ok; Ks2 float2 stride 264==8 mod 32 ->
// (8tg+2g) distinct per 16-lane phase ok; VsH B-frag (8tg+g)%32 ok.
// ---------------------------------------------------------------------------
#define FL_QS  (128 * 132)
#define FL_KS2 (64 * 132 * 2)
#define FL_VS  (64 * 136)
#define FL_PS  (128 * 68)
#define FL_SMEM ((FL_QS + FL_KS2 + FL_VS + FL_PS) * 4)

__global__ __launch_bounds__(256) void flash_tf32_kernel()
{
    extern __shared__ float sm[];
    float*  Qs  = sm;
    float2* Ks2 = (float2*)(sm + FL_QS);
    float*  VsH = sm + FL_QS + FL_KS2;
    float*  Ps  = VsH + FL_VS;

    int bq = blockIdx.x;          // q tile of 128 rows
    int n  = blockIdx.y;
    int kvh = n / GQ;
    int tid = threadIdx.x;
    int warp = tid >> 5, lane = tid & 31;
    int g = lane >> 2, tg = lane & 3;

    // stage Q tile (128 x 128), fp32
    const float* qbase = g_q + ((size_t)n * TT + (size_t)bq * 128) * HD;
#pragma unroll
    for (int it = 0; it < 16; it++) {
        int l = tid + it * 256;
        int row = l >> 5, c4 = l & 31;
        *(float4*)&Qs[row * 132 + c4 * 4] = *(const float4*)(qbase + (size_t)row * HD + c4 * 4);
    }

    float O[16][4];
#pragma unroll
    for (int i = 0; i < 16; i++)
#pragma unroll
        for (int r = 0; r < 4; r++) O[i][r] = 0.f;
    float m0 = -1.0e30f, m1 = -1.0e30f, l0 = 0.f, l1 = 0.f;

    int row_loc0 = warp * 16 + g;       // local q row for c[.][0,1]
    int row_loc1 = row_loc0 + 8;        // for c[.][2,3]
    int qrow0 = bq * 128 + row_loc0;
    int qrow1 = qrow0 + 8;

    int jmax = 2 * bq + 1;
    for (int j = 0; j <= jmax; j++) {
        __syncthreads();   // Qs staged (iter 0) / prev-tile smem reads done
        const float* kb = g_k + ((size_t)kvh * TT + (size_t)j * 64) * HD;
        const float* vb = g_v + ((size_t)kvh * TT + (size_t)j * 64) * HD;
        // stage K pre-split {hi,lo}, V tf32-rounded
#pragma unroll
        for (int it = 0; it < 8; it++) {
            int l = tid + it * 256;
            int row = l >> 5, c4 = l & 31;
            float4 kv = *(const float4*)(kb + (size_t)row * HD + c4 * 4);
            float2 s0 = split2_tf32(kv.x), s1 = split2_tf32(kv.y);
            float2 s2 = split2_tf32(kv.z), s3 = split2_tf32(kv.w);
            float* kd = (float*)&Ks2[row * 132 + c4 * 4];
            *(float4*)kd       = make_float4(s0.x, s0.y, s1.x, s1.y);
            *(float4*)(kd + 4) = make_float4(s2.x, s2.y, s3.x, s3.y);
            float4 vv = *(const float4*)(vb + (size_t)row * HD + c4 * 4);
            *(float4*)&VsH[row * 136 + c4 * 4] =
                make_float4(tf32f(vv.x), tf32f(vv.y), tf32f(vv.z), tf32f(vv.w));
        }
        __syncthreads();

        // ---- S = Q K^T  (16 rows x 64 cols per warp), 3xTF32 ----
        float c[8][4];
#pragma unroll
        for (int nt = 0; nt < 8; nt++)
#pragma unroll
            for (int r = 0; r < 4; r++) c[nt][r] = 0.f;

#pragma unroll
        for (int kc = 0; kc < 16; kc++) {
            uint32_t Ah[4], Al[4];
            split_tf32(Qs[row_loc0 * 132 + kc * 8 + tg],     Ah[0], Al[0]);
            split_tf32(Qs[row_loc1 * 132 + kc * 8 + tg],     Ah[1], Al[1]);
            split_tf32(Qs[row_loc0 * 132 + kc * 8 + tg + 4], Ah[2], Al[2]);
            split_tf32(Qs[row_loc1 * 132 + kc * 8 + tg + 4], Ah[3], Al[3]);
#pragma unroll
            for (int nt = 0; nt < 8; nt++) {
                float2 f0 = Ks2[(nt * 8 + g) * 132 + kc * 8 + tg];
                float2 f1 = Ks2[(nt * 8 + g) * 132 + kc * 8 + tg + 4];
                mma3_tf32(c[nt], Ah, Al,
                          __float_as_uint(f0.x), __float_as_uint(f1.x),
                          __float_as_uint(f0.y), __float_as_uint(f1.y));
            }
        }

        // ---- causal mask (diagonal tiles only) ----
        if (j >= 2 * bq) {
#pragma unroll
            for (int nt = 0; nt < 8; nt++) {
                int col = j * 64 + nt * 8 + tg * 2;
                if (col     > qrow0) c[nt][0] = -1.0e30f;
                if (col + 1 > qrow0) c[nt][1] = -1.0e30f;
                if (col     > qrow1) c[nt][2] = -1.0e30f;
                if (col + 1 > qrow1) c[nt][3] = -1.0e30f;
            }
        }

        // ---- online softmax (quad-local rows) ----
        float mx0 = -1.0e30f, mx1 = -1.0e30f;
#pragma unroll
        for (int nt = 0; nt < 8; nt++) {
            mx0 = fmaxf(mx0, fmaxf(c[nt][0], c[nt][1]));
            mx1 = fmaxf(mx1, fmaxf(c[nt][2], c[nt][3]));
        }
        mx0 = fmaxf(mx0, __shfl_xor_sync(0xFFFFFFFFu, mx0, 1));
        mx0 = fmaxf(mx0, __shfl_xor_sync(0xFFFFFFFFu, mx0, 2));
        mx1 = fmaxf(mx1, __shfl_xor_sync(0xFFFFFFFFu, mx1, 1));
        mx1 = fmaxf(mx1, __shfl_xor_sync(0xFFFFFFFFu, mx1, 2));

        float mn0 = fmaxf(m0, mx0);
        float mn1 = fmaxf(m1, mx1);
        float al0 = __expf(m0 - mn0);
        float al1 = __expf(m1 - mn1);
        float s0 = 0.f, s1 = 0.f;
        // exp, round P to tf32 once; accumulate l from the ROUNDED P so the
        // softmax ratio sees common-mode cancellation.
#pragma unroll
        for (int nt = 0; nt < 8; nt++) {
            c[nt][0] = tf32f(__expf(c[nt][0] - mn0));
            c[nt][1] = tf32f(__expf(c[nt][1] - mn0));
            c[nt][2] = tf32f(__expf(c[nt][2] - mn1));
            c[nt][3] = tf32f(__expf(c[nt][3] - mn1));
            s0 += c[nt][0] + c[nt][1];
            s1 += c[nt][2] + c[nt][3];
        }
        s0 += __shfl_xor_sync(0xFFFFFFFFu, s0, 1);
        s0 += __shfl_xor_sync(0xFFFFFFFFu, s0, 2);
        s1 += __shfl_xor_sync(0xFFFFFFFFu, s1, 1);
        s1 += __shfl_xor_sync(0xFFFFFFFFu, s1, 2);

        l0 = l0 * al0 + s0;  m0 = mn0;
        l1 = l1 * al1 + s1;  m1 = mn1;

#pragma unroll
        for (int i = 0; i < 16; i++) {
            O[i][0] *= al0; O[i][1] *= al0;
            O[i][2] *= al1; O[i][3] *= al1;
        }

        // ---- write P (already tf32-valued), warp-local rows ----
#pragma unroll
        for (int nt = 0; nt < 8; nt++) {
            *(float2*)&Ps[row_loc0 * 68 + nt * 8 + tg * 2] = make_float2(c[nt][0], c[nt][1]);
            *(float2*)&Ps[row_loc1 * 68 + nt * 8 + tg * 2] = make_float2(c[nt][2], c[nt][3]);
        }
        __syncwarp();

        // ---- O += P V  (1xTF32: operands pre-rounded, single MMA) ----
#pragma unroll
        for (int kc = 0; kc < 8; kc++) {
            uint32_t a0 = __float_as_uint(Ps[row_loc0 * 68 + kc * 8 + tg]);
            uint32_t a1 = __float_as_uint(Ps[row_loc1 * 68 + kc * 8 + tg]);
            uint32_t a2 = __float_as_uint(Ps[row_loc0 * 68 + kc * 8 + tg + 4]);
            uint32_t a3 = __float_as_uint(Ps[row_loc1 * 68 + kc * 8 + tg + 4]);
#pragma unroll
            for (int nt = 0; nt < 16; nt++) {
                uint32_t b0 = __float_as_uint(VsH[(kc * 8 + tg)     * 136 + nt * 8 + g]);
                uint32_t b1 = __float_as_uint(VsH[(kc * 8 + tg + 4) * 136 + nt * 8 + g]);
                mma_tf32(O[nt], a0, a1, a2, a3, b0, b1);
            }
        }
    }

    // ---- epilogue: divide by l, write ctx[t][n*H + h] ----
    float inv0 = 1.f / l0;
    float inv1 = 1.f / l1;
    int t0 = bq * 128 + row_loc0;
    int t1 = t0 + 8;
#pragma unroll
    for (int nt = 0; nt < 16; nt++) {
        int col = n * HD + nt * 8 + tg * 2;
        *(float2*)&g_ctx[(size_t)t0 * DD + col] = make_float2(O[nt][0] * inv0, O[nt][1] * inv0);
        *(float2*)&g_ctx[(size_t)t1 * DD + col] = make_float2(O[nt][2] * inv1, O[nt][3] * inv1);
    }
}

// ---------------------------------------------------------------------------

extern "C" void kernel_launch(void* const* d_in, const int* in_sizes, int n_in,
                              void* d_out, int out_size)
{
    const float* x         = (const float*)d_in[0];
    const int*   positions = (const int*)d_in[1];
    const float* wq        = (const float*)d_in[2];
    const float* bq        = (const float*)d_in[3];
    const float* wk        = (const float*)d_in[4];
    const float* bk        = (const float*)d_in[5];
    const float* wv        = (const float*)d_in[6];
    const float* bv        = (const float*)d_in[7];
    const float* wo        = (const float*)d_in[8];
    float* out = (float*)d_out;

    qkv_proj_tf32_kernel<<<dim3(TT / 128, NH + 2 * KH), 256>>>(x, wq, bq, wk, bk, wv, bv);
    rope_kernel<<<dim3(TT, NH + KH), 64>>>(positions);

    cudaFuncSetAttribute(flash_tf32_kernel, cudaFuncAttributeMaxDynamicSharedMemorySize, FL_SMEM);
    flash_tf32_kernel<<<dim3(TT / 128, NH), 256, FL_SMEM>>>();

    out_proj_tf32_kernel<<<dim3(TT / 128, DD / 128), 256>>>(wo, out);
}

// round 12
// speedup vs baseline: 1.8025x; 1.8025x over previous
#include <cuda_runtime.h>
#include <cuda_bf16.h>
#include <math.h>
#include <stdint.h>

#define TT 2048
#define DD 3584
#define NH 28
#define KH 4
#define HD 128
#define GQ 7

// scratch (static __device__ arrays: allocation-free)
__device__ float g_q[(size_t)NH * TT * HD];
__device__ float g_k[(size_t)KH * TT * HD];
__device__ float g_v[(size_t)KH * TT * HD];
__device__ float g_ctx[(size_t)TT * DD];

// ---------------------------------------------------------------------------
// split-bf16 helpers. pack2: low 16 bits = k-even element, high = k-odd.
// x = hi + lo with hi = bf16(x), lo = bf16(x - hi): ~16 effective mantissa bits.
// ---------------------------------------------------------------------------
__device__ __forceinline__ void split_pack(float a, float b, uint32_t& hi, uint32_t& lo)
{
    __nv_bfloat16 ah = __float2bfloat16_rn(a);
    __nv_bfloat16 bh = __float2bfloat16_rn(b);
    float ar = a - __bfloat162float(ah);
    float br = b - __bfloat162float(bh);
    __nv_bfloat16 al = __float2bfloat16_rn(ar);
    __nv_bfloat16 bl = __float2bfloat16_rn(br);
    hi = ((uint32_t)__bfloat16_as_ushort(bh) << 16) | (uint32_t)__bfloat16_as_ushort(ah);
    lo = ((uint32_t)__bfloat16_as_ushort(bl) << 16) | (uint32_t)__bfloat16_as_ushort(al);
}

__device__ __forceinline__ void mma_bf16(float c[4],
                                         uint32_t a0, uint32_t a1, uint32_t a2, uint32_t a3,
                                         uint32_t b0, uint32_t b1)
{
    asm volatile(
        "mma.sync.aligned.m16n8k16.row.col.f32.bf16.bf16.f32 "
        "{%0,%1,%2,%3},{%4,%5,%6,%7},{%8,%9},{%0,%1,%2,%3};"
        : "+f"(c[0]), "+f"(c[1]), "+f"(c[2]), "+f"(c[3])
        : "r"(a0), "r"(a1), "r"(a2), "r"(a3), "r"(b0), "r"(b1));
}

// 3-term compensated product: Al*Bh + Ah*Bl + Ah*Bh  (ll term ~2^-18, dropped)
__device__ __forceinline__ void mma3_bf16(float c[4],
                                          const uint2 a0, const uint2 a1,
                                          const uint2 a2, const uint2 a3,
                                          const uint2 b0, const uint2 b1)
{
    mma_bf16(c, a0.y, a1.y, a2.y, a3.y, b0.x, b1.x);
    mma_bf16(c, a0.x, a1.x, a2.x, a3.x, b0.y, b1.y);
    mma_bf16(c, a0.x, a1.x, a2.x, a3.x, b0.x, b1.x);
}

// ---------------------------------------------------------------------------
// split-bf16 GEMM core: C[128 x 128] = X[128 x DD] * W[DD x 128](slice) (+bias)
// smem: uint2 {hi,lo}, one bf16 k-pair per 16-bit half.
//   Xs[row][20]  (16 kp + 4 pad): A-frag LDS.64, banks (8g+2tg)/phase, CF.
//   Ws[n][20]    (B stored n-major over k-pairs): B-frag banks (40g+2tg)%32
//                distinct per 16-lane phase, CF.
// 256 threads = 8 warps (4m x 2n); warp tile 32 x 64; K-tile 32 (2 MMA ksteps).
// ---------------------------------------------------------------------------
#define GS 20

template<bool HAS_BIAS>
__device__ __forceinline__ void gemm_core_bf16(
    const float* __restrict__ Xbase,
    const float* __restrict__ Wbase, int ldw,
    const float* __restrict__ bias,
    float* __restrict__ Obase, int ldo)
{
    __shared__ uint2 Xs[128 * GS];   // 20480 B
    __shared__ uint2 Ws[128 * GS];   // 20480 B

    int tid  = threadIdx.x;
    int warp = tid >> 5, lane = tid & 31;
    int wm = warp >> 1;        // 0..3 -> rows wm*32
    int wn = warp & 1;         // 0..1 -> cols wn*64
    int g  = lane >> 2;        // 0..7
    int tg = lane & 3;         // 0..3

    float C[2][8][4];
#pragma unroll
    for (int mt = 0; mt < 2; mt++)
#pragma unroll
        for (int nt = 0; nt < 8; nt++)
#pragma unroll
            for (int r = 0; r < 4; r++) C[mt][nt][r] = 0.f;

    for (int k0 = 0; k0 < DD; k0 += 32) {
        // ---- stage X tile (128 x 32): pairs along k within a row ----
#pragma unroll
        for (int it = 0; it < 4; it++) {
            int l = tid + it * 256;
            int row = l >> 3, c4 = l & 7;         // c4: which float4 (4 k)
            float4 v = *(const float4*)(Xbase + (size_t)row * DD + k0 + c4 * 4);
            uint2 p0, p1;
            split_pack(v.x, v.y, p0.x, p0.y);
            split_pack(v.z, v.w, p1.x, p1.y);
            Xs[row * GS + c4 * 2]     = p0;
            Xs[row * GS + c4 * 2 + 1] = p1;
        }
        // ---- stage W tile (32 k x 128 n) into Ws[n][kp]: pairs span 2 k-rows
#pragma unroll
        for (int it = 0; it < 2; it++) {
            int l = tid + it * 256;               // 0..511
            int kp = l & 15;                      // k-pair 0..15
            int nq = l >> 4;                      // 0..31 -> n = 4*nq
            const float* wr0 = Wbase + (size_t)(k0 + 2 * kp)     * ldw + nq * 4;
            const float* wr1 = Wbase + (size_t)(k0 + 2 * kp + 1) * ldw + nq * 4;
            float4 wa = *(const float4*)wr0;
            float4 wb = *(const float4*)wr1;
            uint2 q0, q1, q2, q3;
            split_pack(wa.x, wb.x, q0.x, q0.y);
            split_pack(wa.y, wb.y, q1.x, q1.y);
            split_pack(wa.z, wb.z, q2.x, q2.y);
            split_pack(wa.w, wb.w, q3.x, q3.y);
            Ws[(nq * 4 + 0) * GS + kp] = q0;
            Ws[(nq * 4 + 1) * GS + kp] = q1;
            Ws[(nq * 4 + 2) * GS + kp] = q2;
            Ws[(nq * 4 + 3) * GS + kp] = q3;
        }
        __syncthreads();

#pragma unroll
        for (int kk = 0; kk < 2; kk++) {
            int kpb = kk * 8;
            uint2 A[2][4];
#pragma unroll
            for (int mt = 0; mt < 2; mt++) {
                int r0 = wm * 32 + mt * 16 + g;
                int r1 = r0 + 8;
                A[mt][0] = Xs[r0 * GS + kpb + tg];
                A[mt][1] = Xs[r1 * GS + kpb + tg];
                A[mt][2] = Xs[r0 * GS + kpb + tg + 4];
                A[mt][3] = Xs[r1 * GS + kpb + tg + 4];
            }
#pragma unroll
            for (int nt = 0; nt < 8; nt++) {
                int nb = wn * 64 + nt * 8;
                uint2 b0 = Ws[(nb + g) * GS + kpb + tg];
                uint2 b1 = Ws[(nb + g) * GS + kpb + tg + 4];
                mma3_bf16(C[0][nt], A[0][0], A[0][1], A[0][2], A[0][3], b0, b1);
                mma3_bf16(C[1][nt], A[1][0], A[1][1], A[1][2], A[1][3], b0, b1);
            }
        }
        __syncthreads();
    }

#pragma unroll
    for (int mt = 0; mt < 2; mt++) {
#pragma unroll
        for (int nt = 0; nt < 8; nt++) {
            int row0 = wm * 32 + mt * 16 + g;
            int col  = wn * 64 + nt * 8 + tg * 2;
            float b0v = HAS_BIAS ? bias[col]     : 0.f;
            float b1v = HAS_BIAS ? bias[col + 1] : 0.f;
            *(float2*)&Obase[(size_t)row0 * ldo + col] =
                make_float2(C[mt][nt][0] + b0v, C[mt][nt][1] + b1v);
            *(float2*)&Obase[(size_t)(row0 + 8) * ldo + col] =
                make_float2(C[mt][nt][2] + b0v, C[mt][nt][3] + b1v);
        }
    }
}

// ---------------------------------------------------------------------------
// QKV projection. grid (T/128, 36), block 256.
// ---------------------------------------------------------------------------
__global__ __launch_bounds__(256, 2) void qkv_proj_kernel(
    const float* __restrict__ x,
    const float* __restrict__ wq, const float* __restrict__ bq,
    const float* __restrict__ wk, const float* __restrict__ bk,
    const float* __restrict__ wv, const float* __restrict__ bv)
{
    int z = blockIdx.y;
    const float* w; const float* b; float* out;
    if (z < NH)           { w = wq + (size_t)z * DD * HD;        b = bq + z * HD;        out = g_q + (size_t)z * TT * HD; }
    else if (z < NH + KH) { int c = z - NH;      w = wk + (size_t)c * DD * HD; b = bk + c * HD; out = g_k + (size_t)c * TT * HD; }
    else                  { int c = z - NH - KH; w = wv + (size_t)c * DD * HD; b = bv + c * HD; out = g_v + (size_t)c * TT * HD; }

    int t0 = blockIdx.x * 128;
    gemm_core_bf16<true>(x + (size_t)t0 * DD, w, HD, b, out + (size_t)t0 * HD, HD);
}

// ---------------------------------------------------------------------------
// Output projection. grid (T/128, D/128), block 256.
// ---------------------------------------------------------------------------
__global__ __launch_bounds__(256, 2) void out_proj_kernel(
    const float* __restrict__ wo, float* __restrict__ out)
{
    int t0 = blockIdx.x * 128;
    int n0 = blockIdx.y * 128;
    gemm_core_bf16<false>(g_ctx + (size_t)t0 * DD, wo + n0, DD, nullptr,
                          out + (size_t)t0 * DD + n0, DD);
}

// ---------------------------------------------------------------------------
// RoPE in-place on g_q (with 1/sqrt(H) scale) and g_k. fp64 angle math.
// grid: (T, NH+KH), block 64
// ---------------------------------------------------------------------------
__global__ void rope_kernel(const int* __restrict__ positions)
{
    int t = blockIdx.x;
    int hidx = blockIdx.y;
    int i = threadIdx.x;  // 0..63

    float* base; float scale;
    if (hidx < NH) { base = g_q + ((size_t)hidx * TT + t) * HD; scale = 0.08838834764831845f; }
    else           { base = g_k + ((size_t)(hidx - NH) * TT + t) * HD; scale = 1.0f; }

    int pos = positions[t];
    double inv_freq = pow(1000000.0, -(double)(2 * i) / 128.0);
    double ang = (double)pos * inv_freq;
    double sd, cd;
    sincos(ang, &sd, &cd);
    float c = (float)cd, s = (float)sd;
    float x1 = base[i], x2 = base[i + 64];
    base[i]      = (x1 * c - x2 * s) * scale;
    base[i + 64] = (x2 * c + x1 * s) * scale;
}

// ---------------------------------------------------------------------------
// Flash attention, split-bf16 everywhere (S and PV both 3-MMA compensated).
// grid (T/128, NH), block 256 = 8 warps; warp w owns q-rows [16w, 16w+16).
// smem (uint2 {hi,lo} of bf16 k-pairs):
//   Qs[128 q][68]   kp over h (64 kp + 4 pad)   - A of S, staged once
//   Ks[64 key][68]  kp over h                   - B of S (col=key)
//   Vs[128 h][36]   kp over key (32 kp + 4 pad) - B of PV (col=h)
//   Ps[128 q][36]   kp over key                 - A of PV (from registers)
// Total 178,176 B. All inner-loop frag reads LDS.64, conflict-free per phase.
// ---------------------------------------------------------------------------
#define FQ_S 68
#define FK_S 68
#define FV_S 36
#define FP_S 36
#define FL_QN (128 * FQ_S)
#define FL_KN (64 * FK_S)
#define FL_VN (128 * FV_S)
#define FL_PN (128 * FP_S)
#define FL_SMEM ((FL_QN + FL_KN + FL_VN + FL_PN) * 8)

__global__ __launch_bounds__(256) void flash_bf16_kernel()
{
    extern __shared__ uint2 smu[];
    uint2* Qs = smu;
    uint2* Ks = Qs + FL_QN;
    uint2* Vs = Ks + FL_KN;
    uint2* Ps = Vs + FL_VN;

    int bq = blockIdx.x;          // q tile of 128 rows
    int n  = blockIdx.y;
    int kvh = n / GQ;
    int tid = threadIdx.x;
    int warp = tid >> 5, lane = tid & 31;
    int g = lane >> 2, tg = lane & 3;

    // ---- stage Q tile (128 x 128), pre-split, pairs along h ----
    const float* qbase = g_q + ((size_t)n * TT + (size_t)bq * 128) * HD;
#pragma unroll
    for (int it = 0; it < 16; it++) {
        int l = tid + it * 256;
        int row = l >> 5, c4 = l & 31;
        float4 v = *(const float4*)(qbase + (size_t)row * HD + c4 * 4);
        uint2 p0, p1;
        split_pack(v.x, v.y, p0.x, p0.y);
        split_pack(v.z, v.w, p1.x, p1.y);
        Qs[row * FQ_S + c4 * 2]     = p0;
        Qs[row * FQ_S + c4 * 2 + 1] = p1;
    }

    float O[16][4];
#pragma unroll
    for (int i = 0; i < 16; i++)
#pragma unroll
        for (int r = 0; r < 4; r++) O[i][r] = 0.f;
    float m0 = -1.0e30f, m1 = -1.0e30f, l0 = 0.f, l1 = 0.f;

    int row_loc0 = warp * 16 + g;
    int row_loc1 = row_loc0 + 8;
    int qrow0 = bq * 128 + row_loc0;
    int qrow1 = qrow0 + 8;

    int jmax = 2 * bq + 1;
    for (int j = 0; j <= jmax; j++) {
        __syncthreads();   // Qs staged (iter 0) / prev-tile Ks,Vs,Ps reads done
        const float* kb = g_k + ((size_t)kvh * TT + (size_t)j * 64) * HD;
        const float* vb = g_v + ((size_t)kvh * TT + (size_t)j * 64) * HD;
        // K: rows=key, pairs along h (coalesced reads, CF uint4-equivalent writes)
#pragma unroll
        for (int it = 0; it < 8; it++) {
            int l = tid + it * 256;
            int row = l >> 5, c4 = l & 31;
            float4 v = *(const float4*)(kb + (size_t)row * HD + c4 * 4);
            uint2 p0, p1;
            split_pack(v.x, v.y, p0.x, p0.y);
            split_pack(v.z, v.w, p1.x, p1.y);
            Ks[row * FK_S + c4 * 2]     = p0;
            Ks[row * FK_S + c4 * 2 + 1] = p1;
        }
        // V: transpose to [h][key-pairs]; pairs span two key rows.
        // kp = lane -> CF writes; reads scattered (L2-hot tile).
#pragma unroll
        for (int it = 0; it < 4; it++) {
            int l = tid + it * 256;
            int kp = l & 31;           // key pair 0..31
            int h4 = l >> 5;           // 0..31 -> h = 4*h4
            float4 va = *(const float4*)(vb + (size_t)(2 * kp)     * HD + h4 * 4);
            float4 vc = *(const float4*)(vb + (size_t)(2 * kp + 1) * HD + h4 * 4);
            uint2 q0, q1, q2, q3;
            split_pack(va.x, vc.x, q0.x, q0.y);
            split_pack(va.y, vc.y, q1.x, q1.y);
            split_pack(va.z, vc.z, q2.x, q2.y);
            split_pack(va.w, vc.w, q3.x, q3.y);
            Vs[(h4 * 4 + 0) * FV_S + kp] = q0;
            Vs[(h4 * 4 + 1) * FV_S + kp] = q1;
            Vs[(h4 * 4 + 2) * FV_S + kp] = q2;
            Vs[(h4 * 4 + 3) * FV_S + kp] = q3;
        }
        __syncthreads();

        // ---- S = Q K^T (16 rows x 64 cols per warp), 3-MMA bf16 ----
        float c[8][4];
#pragma unroll
        for (int nt = 0; nt < 8; nt++)
#pragma unroll
            for (int r = 0; r < 4; r++) c[nt][r] = 0.f;

#pragma unroll
        for (int kk = 0; kk < 8; kk++) {
            int kpb = kk * 8;
            uint2 a0 = Qs[row_loc0 * FQ_S + kpb + tg];
            uint2 a1 = Qs[row_loc1 * FQ_S + kpb + tg];
            uint2 a2 = Qs[row_loc0 * FQ_S + kpb + tg + 4];
            uint2 a3 = Qs[row_loc1 * FQ_S + kpb + tg + 4];
#pragma unroll
            for (int nt = 0; nt < 8; nt++) {
                uint2 b0 = Ks[(nt * 8 + g) * FK_S + kpb + tg];
                uint2 b1 = Ks[(nt * 8 + g) * FK_S + kpb + tg + 4];
                mma3_bf16(c[nt], a0, a1, a2, a3, b0, b1);
            }
        }

        // ---- causal mask (diagonal tiles only) ----
        if (j >= 2 * bq) {
#pragma unroll
            for (int nt = 0; nt < 8; nt++) {
                int col = j * 64 + nt * 8 + tg * 2;
                if (col     > qrow0) c[nt][0] = -1.0e30f;
                if (col + 1 > qrow0) c[nt][1] = -1.0e30f;
                if (col     > qrow1) c[nt][2] = -1.0e30f;
                if (col + 1 > qrow1) c[nt][3] = -1.0e30f;
            }
        }

        // ---- online softmax (quad-local rows) ----
        float mx0 = -1.0e30f, mx1 = -1.0e30f;
#pragma unroll
        for (int nt = 0; nt < 8; nt++) {
            mx0 = fmaxf(mx0, fmaxf(c[nt][0], c[nt][1]));
            mx1 = fmaxf(mx1, fmaxf(c[nt][2], c[nt][3]));
        }
        mx0 = fmaxf(mx0, __shfl_xor_sync(0xFFFFFFFFu, mx0, 1));
        mx0 = fmaxf(mx0, __shfl_xor_sync(0xFFFFFFFFu, mx0, 2));
        mx1 = fmaxf(mx1, __shfl_xor_sync(0xFFFFFFFFu, mx1, 1));
        mx1 = fmaxf(mx1, __shfl_xor_sync(0xFFFFFFFFu, mx1, 2));

        float mn0 = fmaxf(m0, mx0);
        float mn1 = fmaxf(m1, mx1);
        float al0 = __expf(m0 - mn0);
        float al1 = __expf(m1 - mn1);
        float s0 = 0.f, s1 = 0.f;
#pragma unroll
        for (int nt = 0; nt < 8; nt++) {
            c[nt][0] = __expf(c[nt][0] - mn0);
            c[nt][1] = __expf(c[nt][1] - mn0);
            c[nt][2] = __expf(c[nt][2] - mn1);
            c[nt][3] = __expf(c[nt][3] - mn1);
            s0 += c[nt][0] + c[nt][1];
            s1 += c[nt][2] + c[nt][3];
        }
        s0 += __shfl_xor_sync(0xFFFFFFFFu, s0, 1);
        s0 += __shfl_xor_sync(0xFFFFFFFFu, s0, 2);
        s1 += __shfl_xor_sync(0xFFFFFFFFu, s1, 1);
        s1 += __shfl_xor_sync(0xFFFFFFFFu, s1, 2);

        l0 = l0 * al0 + s0;  m0 = mn0;
        l1 = l1 * al1 + s1;  m1 = mn1;

#pragma unroll
        for (int i = 0; i < 16; i++) {
            O[i][0] *= al0; O[i][1] *= al0;
            O[i][2] *= al1; O[i][3] *= al1;
        }

        // ---- write P pre-split (pairs c[nt][0,1] are adjacent keys) ----
        // write banks (4g + 4nt + tg): conflict-free per nt.
#pragma unroll
        for (int nt = 0; nt < 8; nt++) {
            uint2 p0, p1;
            split_pack(c[nt][0], c[nt][1], p0.x, p0.y);
            split_pack(c[nt][2], c[nt][3], p1.x, p1.y);
            Ps[row_loc0 * FP_S + nt * 4 + tg] = p0;
            Ps[row_loc1 * FP_S + nt * 4 + tg] = p1;
        }
        __syncwarp();

        // ---- O += P V (16 rows x 128 h per warp), 3-MMA bf16 ----
#pragma unroll
        for (int kk = 0; kk < 4; kk++) {
            int kpb = kk * 8;
            uint2 a0 = Ps[row_loc0 * FP_S + kpb + tg];
            uint2 a1 = Ps[row_loc1 * FP_S + kpb + tg];
            uint2 a2 = Ps[row_loc0 * FP_S + kpb + tg + 4];
            uint2 a3 = Ps[row_loc1 * FP_S + kpb + tg + 4];
#pragma unroll
            for (int nt = 0; nt < 16; nt++) {
                uint2 b0 = Vs[(nt * 8 + g) * FV_S + kpb + tg];
                uint2 b1 = Vs[(nt * 8 + g) * FV_S + kpb + tg + 4];
                mma3_bf16(O[nt], a0, a1, a2, a3, b0, b1);
            }
        }
    }

    // ---- epilogue: divide by l, write ctx[t][n*H + h] ----
    float inv0 = 1.f / l0;
    float inv1 = 1.f / l1;
    int t0 = bq * 128 + row_loc0;
    int t1 = t0 + 8;
#pragma unroll
    for (int nt = 0; nt < 16; nt++) {
        int col = n * HD + nt * 8 + tg * 2;
        *(float2*)&g_ctx[(size_t)t0 * DD + col] = make_float2(O[nt][0] * inv0, O[nt][1] * inv0);
        *(float2*)&g_ctx[(size_t)t1 * DD + col] = make_float2(O[nt][2] * inv1, O[nt][3] * inv1);
    }
}

// ---------------------------------------------------------------------------

extern "C" void kernel_launch(void* const* d_in, const int* in_sizes, int n_in,
                              void* d_out, int out_size)
{
    const float* x         = (const float*)d_in[0];
    const int*   positions = (const int*)d_in[1];
    const float* wq        = (const float*)d_in[2];
    const float* bq        = (const float*)d_in[3];
    const float* wk        = (const float*)d_in[4];
    const float* bk        = (const float*)d_in[5];
    const float* wv        = (const float*)d_in[6];
    const float* bv        = (const float*)d_in[7];
    const float* wo        = (const float*)d_in[8];
    float* out = (float*)d_out;

    qkv_proj_kernel<<<dim3(TT / 128, NH + 2 * KH), 256>>>(x, wq, bq, wk, bk, wv, bv);
    rope_kernel<<<dim3(TT, NH + KH), 64>>>(positions);

    cudaFuncSetAttribute(flash_bf16_kernel, cudaFuncAttributeMaxDynamicSharedMemorySize, FL_SMEM);
    flash_bf16_kernel<<<dim3(TT / 128, NH), 256, FL_SMEM>>>();

    out_proj_kernel<<<dim3(TT / 128, DD / 128), 256>>>(wo, out);
}

// round 16
// speedup vs baseline: 1.8666x; 1.0356x over previous
#include <cuda_runtime.h>
#include <cuda_bf16.h>
#include <math.h>
#include <stdint.h>

#define TT 2048
#define DD 3584
#define NH 28
#define KH 4
#define HD 128
#define GQ 7
#define NZ (NH + 2 * KH)      // 36
#define KT (DD / 32)          // 112 k-tiles of depth 32

// fp32 scratch
__device__ float g_q[(size_t)NH * TT * HD];
__device__ float g_k[(size_t)KH * TT * HD];
__device__ float g_v[(size_t)KH * TT * HD];
__device__ float g_ctx[(size_t)TT * DD];

// pre-split GEMM operands (uint2 = {hi-pair, lo-pair} of bf16, pairs along k)
__device__ uint2 g_xs[(size_t)TT * (DD / 2)];                  // x, pairs along d
__device__ uint2 g_cs[(size_t)TT * (DD / 2)];                  // ctx, pairs along d
__device__ uint2 g_ws[(size_t)NZ * KT * 128 * 16];             // qkv W, tile-major
__device__ uint2 g_wos[(size_t)(DD / 128) * KT * 128 * 16];    // wo, tile-major

// ---------------------------------------------------------------------------
// split-bf16 helpers. pack2: low 16 bits = k-even element, high = k-odd.
// ---------------------------------------------------------------------------
__device__ __forceinline__ void split_pack(float a, float b, uint32_t& hi, uint32_t& lo)
{
    __nv_bfloat16 ah = __float2bfloat16_rn(a);
    __nv_bfloat16 bh = __float2bfloat16_rn(b);
    float ar = a - __bfloat162float(ah);
    float br = b - __bfloat162float(bh);
    __nv_bfloat16 al = __float2bfloat16_rn(ar);
    __nv_bfloat16 bl = __float2bfloat16_rn(br);
    hi = ((uint32_t)__bfloat16_as_ushort(bh) << 16) | (uint32_t)__bfloat16_as_ushort(ah);
    lo = ((uint32_t)__bfloat16_as_ushort(bl) << 16) | (uint32_t)__bfloat16_as_ushort(al);
}

__device__ __forceinline__ void mma_bf16(float c[4],
                                         uint32_t a0, uint32_t a1, uint32_t a2, uint32_t a3,
                                         uint32_t b0, uint32_t b1)
{
    asm volatile(
        "mma.sync.aligned.m16n8k16.row.col.f32.bf16.bf16.f32 "
        "{%0,%1,%2,%3},{%4,%5,%6,%7},{%8,%9},{%0,%1,%2,%3};"
        : "+f"(c[0]), "+f"(c[1]), "+f"(c[2]), "+f"(c[3])
        : "r"(a0), "r"(a1), "r"(a2), "r"(a3), "r"(b0), "r"(b1));
}

__device__ __forceinline__ void mma3_bf16(float c[4],
                                          const uint2 a0, const uint2 a1,
                                          const uint2 a2, const uint2 a3,
                                          const uint2 b0, const uint2 b1)
{
    mma_bf16(c, a0.y, a1.y, a2.y, a3.y, b0.x, b1.x);
    mma_bf16(c, a0.x, a1.x, a2.x, a3.x, b0.y, b1.y);
    mma_bf16(c, a0.x, a1.x, a2.x, a3.x, b0.x, b1.x);
}

// ---------------------------------------------------------------------------
// Pre-split passes (GEMM operands only). All __device__ globals referenced
// INSIDE device code (host passing of __device__ symbols was the R13/R14 bug).
// ---------------------------------------------------------------------------

// x (harness input) -> g_xs
__global__ void presplit_x_kernel(const float* __restrict__ src)
{
    int i = blockIdx.x * blockDim.x + threadIdx.x;   // over float4s
    float4 v = ((const float4*)src)[i];
    uint2 p0, p1;
    split_pack(v.x, v.y, p0.x, p0.y);
    split_pack(v.z, v.w, p1.x, p1.y);
    g_xs[(size_t)i * 2]     = p0;
    g_xs[(size_t)i * 2 + 1] = p1;
}

// g_ctx -> g_cs
__global__ void presplit_ctx_kernel()
{
    int i = blockIdx.x * blockDim.x + threadIdx.x;   // over float4s
    float4 v = ((const float4*)g_ctx)[i];
    uint2 p0, p1;
    split_pack(v.x, v.y, p0.x, p0.y);
    split_pack(v.z, v.w, p1.x, p1.y);
    g_cs[(size_t)i * 2]     = p0;
    g_cs[(size_t)i * 2 + 1] = p1;
}

// qkv weights -> tile-major [z][kt][n][kp]
__global__ __launch_bounds__(512) void presplit_wqkv_kernel(
    const float* __restrict__ wq, const float* __restrict__ wk, const float* __restrict__ wv)
{
    int z = blockIdx.y, kt = blockIdx.x;
    const float* w;
    if (z < NH)           w = wq + (size_t)z * DD * HD;
    else if (z < NH + KH) w = wk + (size_t)(z - NH) * DD * HD;
    else                  w = wv + (size_t)(z - NH - KH) * DD * HD;

    int tid = threadIdx.x;
    int nq = tid & 31, kp = tid >> 5;        // nq: n/4, kp: k-pair 0..15
    int k0 = kt * 32;
    float4 wa = *(const float4*)(w + (size_t)(k0 + 2 * kp)     * HD + nq * 4);
    float4 wb = *(const float4*)(w + (size_t)(k0 + 2 * kp + 1) * HD + nq * 4);
    uint2* dst = g_ws + (size_t)(z * KT + kt) * 2048;
    uint2 q0, q1, q2, q3;
    split_pack(wa.x, wb.x, q0.x, q0.y);
    split_pack(wa.y, wb.y, q1.x, q1.y);
    split_pack(wa.z, wb.z, q2.x, q2.y);
    split_pack(wa.w, wb.w, q3.x, q3.y);
    dst[(nq * 4 + 0) * 16 + kp] = q0;
    dst[(nq * 4 + 1) * 16 + kp] = q1;
    dst[(nq * 4 + 2) * 16 + kp] = q2;
    dst[(nq * 4 + 3) * 16 + kp] = q3;
}

// wo -> tile-major [nblk][kt][n][kp]
__global__ __launch_bounds__(512) void presplit_wo_kernel(const float* __restrict__ wo)
{
    int nblk = blockIdx.y, kt = blockIdx.x;
    int tid = threadIdx.x;
    int nq = tid & 31, kp = tid >> 5;
    int k0 = kt * 32;
    const float* w = wo + nblk * 128;
    float4 wa = *(const float4*)(w + (size_t)(k0 + 2 * kp)     * DD + nq * 4);
    float4 wb = *(const float4*)(w + (size_t)(k0 + 2 * kp + 1) * DD + nq * 4);
    uint2* dst = g_wos + (size_t)(nblk * KT + kt) * 2048;
    uint2 q0, q1, q2, q3;
    split_pack(wa.x, wb.x, q0.x, q0.y);
    split_pack(wa.y, wb.y, q1.x, q1.y);
    split_pack(wa.z, wb.z, q2.x, q2.y);
    split_pack(wa.w, wb.w, q3.x, q3.y);
    dst[(nq * 4 + 0) * 16 + kp] = q0;
    dst[(nq * 4 + 1) * 16 + kp] = q1;
    dst[(nq * 4 + 2) * 16 + kp] = q2;
    dst[(nq * 4 + 3) * 16 + kp] = q3;
}

// ---------------------------------------------------------------------------
// split-bf16 GEMM core, pure-copy staging (operands pre-split in gmem).
// Inner MMA/LDS loop and epilogue identical to R12 (known-good).
// ---------------------------------------------------------------------------
#define GS 20   // smem row stride in uint2 (16 used + 4 pad)

template<bool HAS_BIAS>
__device__ __forceinline__ void gemm_core(
    const uint2* __restrict__ Xg,
    const uint2* __restrict__ Wtiles,
    const float* __restrict__ bias,
    float* __restrict__ Obase, int ldo)
{
    __shared__ uint2 Xs[128 * GS];
    __shared__ uint2 Ws[128 * GS];

    int tid  = threadIdx.x;
    int warp = tid >> 5, lane = tid & 31;
    int wm = warp >> 1;
    int wn = warp & 1;
    int g  = lane >> 2;
    int tg = lane & 3;

    float C[2][8][4];
#pragma unroll
    for (int mt = 0; mt < 2; mt++)
#pragma unroll
        for (int nt = 0; nt < 8; nt++)
#pragma unroll
            for (int r = 0; r < 4; r++) C[mt][nt][r] = 0.f;

    for (int kt = 0; kt < KT; kt++) {
        // X tile copy: 128 rows x 8 uint4
#pragma unroll
        for (int it = 0; it < 4; it++) {
            int l = tid + it * 256;
            int row = l >> 3, p = l & 7;
            ((uint4*)&Xs[row * GS])[p] =
                ((const uint4*)&Xg[(size_t)row * (DD / 2) + kt * 16])[p];
        }
        // W tile copy: contiguous 1024 uint4
        const uint2* wt = Wtiles + (size_t)kt * 2048;
#pragma unroll
        for (int it = 0; it < 4; it++) {
            int l = tid + it * 256;
            int n = l >> 3, p = l & 7;
            ((uint4*)&Ws[n * GS])[p] = ((const uint4*)(wt + n * 16))[p];
        }
        __syncthreads();

#pragma unroll
        for (int kk = 0; kk < 2; kk++) {
            int kpb = kk * 8;
            uint2 A[2][4];
#pragma unroll
            for (int mt = 0; mt < 2; mt++) {
                int r0 = wm * 32 + mt * 16 + g;
                int r1 = r0 + 8;
                A[mt][0] = Xs[r0 * GS + kpb + tg];
                A[mt][1] = Xs[r1 * GS + kpb + tg];
                A[mt][2] = Xs[r0 * GS + kpb + tg + 4];
                A[mt][3] = Xs[r1 * GS + kpb + tg + 4];
            }
#pragma unroll
            for (int nt = 0; nt < 8; nt++) {
                int nb = wn * 64 + nt * 8;
                uint2 b0 = Ws[(nb + g) * GS + kpb + tg];
                uint2 b1 = Ws[(nb + g) * GS + kpb + tg + 4];
                mma3_bf16(C[0][nt], A[0][0], A[0][1], A[0][2], A[0][3], b0, b1);
                mma3_bf16(C[1][nt], A[1][0], A[1][1], A[1][2], A[1][3], b0, b1);
            }
        }
        __syncthreads();
    }

#pragma unroll
    for (int mt = 0; mt < 2; mt++) {
#pragma unroll
        for (int nt = 0; nt < 8; nt++) {
            int row0 = wm * 32 + mt * 16 + g;
            int col  = wn * 64 + nt * 8 + tg * 2;
            float b0v = HAS_BIAS ? bias[col]     : 0.f;
            float b1v = HAS_BIAS ? bias[col + 1] : 0.f;
            *(float2*)&Obase[(size_t)row0 * ldo + col] =
                make_float2(C[mt][nt][0] + b0v, C[mt][nt][1] + b1v);
            *(float2*)&Obase[(size_t)(row0 + 8) * ldo + col] =
                make_float2(C[mt][nt][2] + b0v, C[mt][nt][3] + b1v);
        }
    }
}

// ---------------------------------------------------------------------------
// QKV projection. grid (T/128, 36), block 256.
// ---------------------------------------------------------------------------
__global__ __launch_bounds__(256, 2) void qkv_proj_kernel(
    const float* __restrict__ bq, const float* __restrict__ bk,
    const float* __restrict__ bv)
{
    int z = blockIdx.y;
    const float* b; float* out;
    if (z < NH)           { b = bq + z * HD;              out = g_q + (size_t)z * TT * HD; }
    else if (z < NH + KH) { int c = z - NH;      b = bk + c * HD; out = g_k + (size_t)c * TT * HD; }
    else                  { int c = z - NH - KH; b = bv + c * HD; out = g_v + (size_t)c * TT * HD; }

    int t0 = blockIdx.x * 128;
    gemm_core<true>(g_xs + (size_t)t0 * (DD / 2),
                    g_ws + (size_t)z * KT * 2048,
                    b, out + (size_t)t0 * HD, HD);
}

// ---------------------------------------------------------------------------
// Output projection. grid (T/128, D/128), block 256.
// ---------------------------------------------------------------------------
__global__ __launch_bounds__(256, 2) void out_proj_kernel(float* __restrict__ out)
{
    int t0 = blockIdx.x * 128;
    int nblk = blockIdx.y;
    gemm_core<false>(g_cs + (size_t)t0 * (DD / 2),
                     g_wos + (size_t)nblk * KT * 2048,
                     nullptr, out + (size_t)t0 * DD + nblk * 128, DD);
}

// ---------------------------------------------------------------------------
// RoPE in-place on g_q (with 1/sqrt(H) scale) and g_k. fp64 angle math.
// grid: (T, NH+KH), block 64   (identical to R12)
// ---------------------------------------------------------------------------
__global__ void rope_kernel(const int* __restrict__ positions)
{
    int t = blockIdx.x;
    int hidx = blockIdx.y;
    int i = threadIdx.x;  // 0..63

    float* base; float scale;
    if (hidx < NH) { base = g_q + ((size_t)hidx * TT + t) * HD; scale = 0.08838834764831845f; }
    else           { base = g_k + ((size_t)(hidx - NH) * TT + t) * HD; scale = 1.0f; }

    int pos = positions[t];
    double inv_freq = pow(1000000.0, -(double)(2 * i) / 128.0);
    double ang = (double)pos * inv_freq;
    double sd, cd;
    sincos(ang, &sd, &cd);
    float c = (float)cd, s = (float)sd;
    float x1 = base[i], x2 = base[i + 64];
    base[i]      = (x1 * c - x2 * s) * scale;
    base[i + 64] = (x2 * c + x1 * s) * scale;
}

// ---------------------------------------------------------------------------
// Flash attention, split-bf16 (identical to R12, known-good).
// grid (T/128, NH), block 256 = 8 warps; warp w owns q-rows [16w, 16w+16).
// ---------------------------------------------------------------------------
#define FQ_S 68
#define FK_S 68
#define FV_S 36
#define FP_S 36
#define FL_QN (128 * FQ_S)
#define FL_KN (64 * FK_S)
#define FL_VN (128 * FV_S)
#define FL_PN (128 * FP_S)
#define FL_SMEM ((FL_QN + FL_KN + FL_VN + FL_PN) * 8)

__global__ __launch_bounds__(256) void flash_bf16_kernel()
{
    extern __shared__ uint2 smu[];
    uint2* Qs = smu;
    uint2* Ks = Qs + FL_QN;
    uint2* Vs = Ks + FL_KN;
    uint2* Ps = Vs + FL_VN;

    int bq = blockIdx.x;
    int n  = blockIdx.y;
    int kvh = n / GQ;
    int tid = threadIdx.x;
    int warp = tid >> 5, lane = tid & 31;
    int g = lane >> 2, tg = lane & 3;

    // ---- stage Q tile (128 x 128), pre-split, pairs along h ----
    const float* qbase = g_q + ((size_t)n * TT + (size_t)bq * 128) * HD;
#pragma unroll
    for (int it = 0; it < 16; it++) {
        int l = tid + it * 256;
        int row = l >> 5, c4 = l & 31;
        float4 v = *(const float4*)(qbase + (size_t)row * HD + c4 * 4);
        uint2 p0, p1;
        split_pack(v.x, v.y, p0.x, p0.y);
        split_pack(v.z, v.w, p1.x, p1.y);
        Qs[row * FQ_S + c4 * 2]     = p0;
        Qs[row * FQ_S + c4 * 2 + 1] = p1;
    }

    float O[16][4];
#pragma unroll
    for (int i = 0; i < 16; i++)
#pragma unroll
        for (int r = 0; r < 4; r++) O[i][r] = 0.f;
    float m0 = -1.0e30f, m1 = -1.0e30f, l0 = 0.f, l1 = 0.f;

    int row_loc0 = warp * 16 + g;
    int row_loc1 = row_loc0 + 8;
    int qrow0 = bq * 128 + row_loc0;
    int qrow1 = qrow0 + 8;

    int jmax = 2 * bq + 1;
    for (int j = 0; j <= jmax; j++) {
        __syncthreads();
        const float* kb = g_k + ((size_t)kvh * TT + (size_t)j * 64) * HD;
        const float* vb = g_v + ((size_t)kvh * TT + (size_t)j * 64) * HD;
#pragma unroll
        for (int it = 0; it < 8; it++) {
            int l = tid + it * 256;
            int row = l >> 5, c4 = l & 31;
            float4 v = *(const float4*)(kb + (size_t)row * HD + c4 * 4);
            uint2 p0, p1;
            split_pack(v.x, v.y, p0.x, p0.y);
            split_pack(v.z, v.w, p1.x, p1.y);
            Ks[row * FK_S + c4 * 2]     = p0;
            Ks[row * FK_S + c4 * 2 + 1] = p1;
        }
#pragma unroll
        for (int it = 0; it < 4; it++) {
            int l = tid + it * 256;
            int kp = l & 31;
            int h4 = l >> 5;
            float4 va = *(const float4*)(vb + (size_t)(2 * kp)     * HD + h4 * 4);
            float4 vc = *(const float4*)(vb + (size_t)(2 * kp + 1) * HD + h4 * 4);
            uint2 q0, q1, q2, q3;
            split_pack(va.x, vc.x, q0.x, q0.y);
            split_pack(va.y, vc.y, q1.x, q1.y);
            split_pack(va.z, vc.z, q2.x, q2.y);
            split_pack(va.w, vc.w, q3.x, q3.y);
            Vs[(h4 * 4 + 0) * FV_S + kp] = q0;
            Vs[(h4 * 4 + 1) * FV_S + kp] = q1;
            Vs[(h4 * 4 + 2) * FV_S + kp] = q2;
            Vs[(h4 * 4 + 3) * FV_S + kp] = q3;
        }
        __syncthreads();

        // ---- S = Q K^T (16 rows x 64 cols per warp), 3-MMA bf16 ----
        float c[8][4];
#pragma unroll
        for (int nt = 0; nt < 8; nt++)
#pragma unroll
            for (int r = 0; r < 4; r++) c[nt][r] = 0.f;

#pragma unroll
        for (int kk = 0; kk < 8; kk++) {
            int kpb = kk * 8;
            uint2 a0 = Qs[row_loc0 * FQ_S + kpb + tg];
            uint2 a1 = Qs[row_loc1 * FQ_S + kpb + tg];
            uint2 a2 = Qs[row_loc0 * FQ_S + kpb + tg + 4];
            uint2 a3 = Qs[row_loc1 * FQ_S + kpb + tg + 4];
#pragma unroll
            for (int nt = 0; nt < 8; nt++) {
                uint2 b0 = Ks[(nt * 8 + g) * FK_S + kpb + tg];
                uint2 b1 = Ks[(nt * 8 + g) * FK_S + kpb + tg + 4];
                mma3_bf16(c[nt], a0, a1, a2, a3, b0, b1);
            }
        }

        // ---- causal mask (diagonal tiles only) ----
        if (j >= 2 * bq) {
#pragma unroll
            for (int nt = 0; nt < 8; nt++) {
                int col = j * 64 + nt * 8 + tg * 2;
                if (col     > qrow0) c[nt][0] = -1.0e30f;
                if (col + 1 > qrow0) c[nt][1] = -1.0e30f;
                if (col     > qrow1) c[nt][2] = -1.0e30f;
                if (col + 1 > qrow1) c[nt][3] = -1.0e30f;
            }
        }

        // ---- online softmax (quad-local rows) ----
        float mx0 = -1.0e30f, mx1 = -1.0e30f;
#pragma unroll
        for (int nt = 0; nt < 8; nt++) {
            mx0 = fmaxf(mx0, fmaxf(c[nt][0], c[nt][1]));
            mx1 = fmaxf(mx1, fmaxf(c[nt][2], c[nt][3]));
        }
        mx0 = fmaxf(mx0, __shfl_xor_sync(0xFFFFFFFFu, mx0, 1));
        mx0 = fmaxf(mx0, __shfl_xor_sync(0xFFFFFFFFu, mx0, 2));
        mx1 = fmaxf(mx1, __shfl_xor_sync(0xFFFFFFFFu, mx1, 1));
        mx1 = fmaxf(mx1, __shfl_xor_sync(0xFFFFFFFFu, mx1, 2));

        float mn0 = fmaxf(m0, mx0);
        float mn1 = fmaxf(m1, mx1);
        float al0 = __expf(m0 - mn0);
        float al1 = __expf(m1 - mn1);
        float s0 = 0.f, s1 = 0.f;
#pragma unroll
        for (int nt = 0; nt < 8; nt++) {
            c[nt][0] = __expf(c[nt][0] - mn0);
            c[nt][1] = __expf(c[nt][1] - mn0);
            c[nt][2] = __expf(c[nt][2] - mn1);
            c[nt][3] = __expf(c[nt][3] - mn1);
            s0 += c[nt][0] + c[nt][1];
            s1 += c[nt][2] + c[nt][3];
        }
        s0 += __shfl_xor_sync(0xFFFFFFFFu, s0, 1);
        s0 += __shfl_xor_sync(0xFFFFFFFFu, s0, 2);
        s1 += __shfl_xor_sync(0xFFFFFFFFu, s1, 1);
        s1 += __shfl_xor_sync(0xFFFFFFFFu, s1, 2);

        l0 = l0 * al0 + s0;  m0 = mn0;
        l1 = l1 * al1 + s1;  m1 = mn1;

#pragma unroll
        for (int i = 0; i < 16; i++) {
            O[i][0] *= al0; O[i][1] *= al0;
            O[i][2] *= al1; O[i][3] *= al1;
        }

        // ---- write P pre-split ----
#pragma unroll
        for (int nt = 0; nt < 8; nt++) {
            uint2 p0, p1;
            split_pack(c[nt][0], c[nt][1], p0.x, p0.y);
            split_pack(c[nt][2], c[nt][3], p1.x, p1.y);
            Ps[row_loc0 * FP_S + nt * 4 + tg] = p0;
            Ps[row_loc1 * FP_S + nt * 4 + tg] = p1;
        }
        __syncwarp();

        // ---- O += P V (16 rows x 128 h per warp), 3-MMA bf16 ----
#pragma unroll
        for (int kk = 0; kk < 4; kk++) {
            int kpb = kk * 8;
            uint2 a0 = Ps[row_loc0 * FP_S + kpb + tg];
            uint2 a1 = Ps[row_loc1 * FP_S + kpb + tg];
            uint2 a2 = Ps[row_loc0 * FP_S + kpb + tg + 4];
            uint2 a3 = Ps[row_loc1 * FP_S + kpb + tg + 4];
#pragma unroll
            for (int nt = 0; nt < 16; nt++) {
                uint2 b0 = Vs[(nt * 8 + g) * FV_S + kpb + tg];
                uint2 b1 = Vs[(nt * 8 + g) * FV_S + kpb + tg + 4];
                mma3_bf16(O[nt], a0, a1, a2, a3, b0, b1);
            }
        }
    }

    // ---- epilogue: divide by l, write ctx[t][n*H + h] ----
    float inv0 = 1.f / l0;
    float inv1 = 1.f / l1;
    int t0 = bq * 128 + row_loc0;
    int t1 = t0 + 8;
#pragma unroll
    for (int nt = 0; nt < 16; nt++) {
        int col = n * HD + nt * 8 + tg * 2;
        *(float2*)&g_ctx[(size_t)t0 * DD + col] = make_float2(O[nt][0] * inv0, O[nt][1] * inv0);
        *(float2*)&g_ctx[(size_t)t1 * DD + col] = make_float2(O[nt][2] * inv1, O[nt][3] * inv1);
    }
}

// ---------------------------------------------------------------------------

extern "C" void kernel_launch(void* const* d_in, const int* in_sizes, int n_in,
                              void* d_out, int out_size)
{
    const float* x         = (const float*)d_in[0];
    const int*   positions = (const int*)d_in[1];
    const float* wq        = (const float*)d_in[2];
    const float* bq        = (const float*)d_in[3];
    const float* wk        = (const float*)d_in[4];
    const float* bk        = (const float*)d_in[5];
    const float* wv        = (const float*)d_in[6];
    const float* bv        = (const float*)d_in[7];
    const float* wo        = (const float*)d_in[8];
    float* out = (float*)d_out;

    presplit_wqkv_kernel<<<dim3(KT, NZ), 512>>>(wq, wk, wv);
    presplit_wo_kernel<<<dim3(KT, DD / 128), 512>>>(wo);
    presplit_x_kernel<<<TT * DD / 4 / 256, 256>>>(x);

    qkv_proj_kernel<<<dim3(TT / 128, NZ), 256>>>(bq, bk, bv);
    rope_kernel<<<dim3(TT, NH + KH), 64>>>(positions);

    cudaFuncSetAttribute(flash_bf16_kernel, cudaFuncAttributeMaxDynamicSharedMemorySize, FL_SMEM);
    flash_bf16_kernel<<<dim3(TT / 128, NH), 256, FL_SMEM>>>();

    presplit_ctx_kernel<<<TT * DD / 4 / 256, 256>>>();
    out_proj_kernel<<<dim3(TT / 128, DD / 128), 256>>>(out);
}

// round 17
// speedup vs baseline: 1.9649x; 1.0527x over previous
#include <cuda_runtime.h>
#include <cuda_bf16.h>
#include <math.h>
#include <stdint.h>

#define TT 2048
#define DD 3584
#define NH 28
#define KH 4
#define HD 128
#define GQ 7
#define NZ (NH + 2 * KH)      // 36
#define KT (DD / 32)          // 112 k-tiles of depth 32

// fp32 scratch
__device__ float g_q[(size_t)NH * TT * HD];
__device__ float g_k[(size_t)KH * TT * HD];
__device__ float g_v[(size_t)KH * TT * HD];
__device__ float g_ctx[(size_t)TT * DD];

// pre-split operands (uint2 = {hi-pair, lo-pair} of bf16, pairs along k)
__device__ uint2 g_xs[(size_t)TT * (DD / 2)];                  // x, pairs along d
__device__ uint2 g_cs[(size_t)TT * (DD / 2)];                  // ctx, pairs along d
__device__ uint2 g_ws[(size_t)NZ * KT * 128 * 16];             // qkv W, tile-major
__device__ uint2 g_wos[(size_t)(DD / 128) * KT * 128 * 16];    // wo, tile-major
__device__ uint2 g_qs[(size_t)NH * TT * (HD / 2)];             // roped Q, pairs along h
__device__ uint2 g_ks[(size_t)KH * TT * (HD / 2)];             // roped K, pairs along h
__device__ uint2 g_vs[(size_t)KH * (TT / 64) * HD * 32];       // V, per-tile [h][key-pair]

// ---------------------------------------------------------------------------
// split-bf16 helpers. pack2: low 16 bits = k-even element, high = k-odd.
// ---------------------------------------------------------------------------
__device__ __forceinline__ void split_pack(float a, float b, uint32_t& hi, uint32_t& lo)
{
    __nv_bfloat16 ah = __float2bfloat16_rn(a);
    __nv_bfloat16 bh = __float2bfloat16_rn(b);
    float ar = a - __bfloat162float(ah);
    float br = b - __bfloat162float(bh);
    __nv_bfloat16 al = __float2bfloat16_rn(ar);
    __nv_bfloat16 bl = __float2bfloat16_rn(br);
    hi = ((uint32_t)__bfloat16_as_ushort(bh) << 16) | (uint32_t)__bfloat16_as_ushort(ah);
    lo = ((uint32_t)__bfloat16_as_ushort(bl) << 16) | (uint32_t)__bfloat16_as_ushort(al);
}

__device__ __forceinline__ void mma_bf16(float c[4],
                                         uint32_t a0, uint32_t a1, uint32_t a2, uint32_t a3,
                                         uint32_t b0, uint32_t b1)
{
    asm volatile(
        "mma.sync.aligned.m16n8k16.row.col.f32.bf16.bf16.f32 "
        "{%0,%1,%2,%3},{%4,%5,%6,%7},{%8,%9},{%0,%1,%2,%3};"
        : "+f"(c[0]), "+f"(c[1]), "+f"(c[2]), "+f"(c[3])
        : "r"(a0), "r"(a1), "r"(a2), "r"(a3), "r"(b0), "r"(b1));
}

__device__ __forceinline__ void mma3_bf16(float c[4],
                                          const uint2 a0, const uint2 a1,
                                          const uint2 a2, const uint2 a3,
                                          const uint2 b0, const uint2 b1)
{
    mma_bf16(c, a0.y, a1.y, a2.y, a3.y, b0.x, b1.x);
    mma_bf16(c, a0.x, a1.x, a2.x, a3.x, b0.y, b1.y);
    mma_bf16(c, a0.x, a1.x, a2.x, a3.x, b0.x, b1.x);
}

// ---------------------------------------------------------------------------
// Pre-split passes. All __device__ globals referenced INSIDE device code.
// ---------------------------------------------------------------------------

// x (harness input) -> g_xs
__global__ void presplit_x_kernel(const float* __restrict__ src)
{
    int i = blockIdx.x * blockDim.x + threadIdx.x;   // over float4s
    float4 v = ((const float4*)src)[i];
    uint2 p0, p1;
    split_pack(v.x, v.y, p0.x, p0.y);
    split_pack(v.z, v.w, p1.x, p1.y);
    g_xs[(size_t)i * 2]     = p0;
    g_xs[(size_t)i * 2 + 1] = p1;
}

// g_ctx -> g_cs
__global__ void presplit_ctx_kernel()
{
    int i = blockIdx.x * blockDim.x + threadIdx.x;   // over float4s
    float4 v = ((const float4*)g_ctx)[i];
    uint2 p0, p1;
    split_pack(v.x, v.y, p0.x, p0.y);
    split_pack(v.z, v.w, p1.x, p1.y);
    g_cs[(size_t)i * 2]     = p0;
    g_cs[(size_t)i * 2 + 1] = p1;
}

// qkv weights -> tile-major [z][kt][n][kp]
__global__ __launch_bounds__(512) void presplit_wqkv_kernel(
    const float* __restrict__ wq, const float* __restrict__ wk, const float* __restrict__ wv)
{
    int z = blockIdx.y, kt = blockIdx.x;
    const float* w;
    if (z < NH)           w = wq + (size_t)z * DD * HD;
    else if (z < NH + KH) w = wk + (size_t)(z - NH) * DD * HD;
    else                  w = wv + (size_t)(z - NH - KH) * DD * HD;

    int tid = threadIdx.x;
    int nq = tid & 31, kp = tid >> 5;        // nq: n/4, kp: k-pair 0..15
    int k0 = kt * 32;
    float4 wa = *(const float4*)(w + (size_t)(k0 + 2 * kp)     * HD + nq * 4);
    float4 wb = *(const float4*)(w + (size_t)(k0 + 2 * kp + 1) * HD + nq * 4);
    uint2* dst = g_ws + (size_t)(z * KT + kt) * 2048;
    uint2 q0, q1, q2, q3;
    split_pack(wa.x, wb.x, q0.x, q0.y);
    split_pack(wa.y, wb.y, q1.x, q1.y);
    split_pack(wa.z, wb.z, q2.x, q2.y);
    split_pack(wa.w, wb.w, q3.x, q3.y);
    dst[(nq * 4 + 0) * 16 + kp] = q0;
    dst[(nq * 4 + 1) * 16 + kp] = q1;
    dst[(nq * 4 + 2) * 16 + kp] = q2;
    dst[(nq * 4 + 3) * 16 + kp] = q3;
}

// wo -> tile-major [nblk][kt][n][kp]
__global__ __launch_bounds__(512) void presplit_wo_kernel(const float* __restrict__ wo)
{
    int nblk = blockIdx.y, kt = blockIdx.x;
    int tid = threadIdx.x;
    int nq = tid & 31, kp = tid >> 5;
    int k0 = kt * 32;
    const float* w = wo + nblk * 128;
    float4 wa = *(const float4*)(w + (size_t)(k0 + 2 * kp)     * DD + nq * 4);
    float4 wb = *(const float4*)(w + (size_t)(k0 + 2 * kp + 1) * DD + nq * 4);
    uint2* dst = g_wos + (size_t)(nblk * KT + kt) * 2048;
    uint2 q0, q1, q2, q3;
    split_pack(wa.x, wb.x, q0.x, q0.y);
    split_pack(wa.y, wb.y, q1.x, q1.y);
    split_pack(wa.z, wb.z, q2.x, q2.y);
    split_pack(wa.w, wb.w, q3.x, q3.y);
    dst[(nq * 4 + 0) * 16 + kp] = q0;
    dst[(nq * 4 + 1) * 16 + kp] = q1;
    dst[(nq * 4 + 2) * 16 + kp] = q2;
    dst[(nq * 4 + 3) * 16 + kp] = q3;
}

// RoPE fused with split: reads g_q/g_k fp32 (identical math to R12/R16 rope),
// writes g_qs/g_ks pre-split (pairs along h).
// grid (T, NH+KH), block 32; thread i handles h = {2i,2i+1} and {64+2i,65+2i}.
__global__ void rope_split_kernel(const int* __restrict__ positions)
{
    int t = blockIdx.x;
    int hidx = blockIdx.y;
    int i = threadIdx.x;  // 0..31

    const float* base; uint2* dst; float scale;
    if (hidx < NH) {
        base = g_q + ((size_t)hidx * TT + t) * HD;
        dst  = g_qs + ((size_t)hidx * TT + t) * 64;
        scale = 0.08838834764831845f;
    } else {
        int c = hidx - NH;
        base = g_k + ((size_t)c * TT + t) * HD;
        dst  = g_ks + ((size_t)c * TT + t) * 64;
        scale = 1.0f;
    }

    int pos = positions[t];
    float o[4];
#pragma unroll
    for (int u = 0; u < 2; u++) {
        int h = 2 * i + u;                       // freq index 0..63
        double inv_freq = pow(1000000.0, -(double)(2 * h) / 128.0);
        double ang = (double)pos * inv_freq;
        double sd, cd;
        sincos(ang, &sd, &cd);
        float c_ = (float)cd, s_ = (float)sd;
        float x1 = base[h], x2 = base[h + 64];
        o[u]     = (x1 * c_ - x2 * s_) * scale;
        o[2 + u] = (x2 * c_ + x1 * s_) * scale;
    }
    uint2 p0, p1;
    split_pack(o[0], o[1], p0.x, p0.y);
    split_pack(o[2], o[3], p1.x, p1.y);
    dst[i]      = p0;   // h-pair (2i, 2i+1)
    dst[32 + i] = p1;   // h-pair (64+2i, 65+2i)
}

// V -> per-64-key-tile transposed split layout [kvh][jt][h][key-pair]
__global__ __launch_bounds__(256) void presplit_v_kernel()
{
    int j = blockIdx.x;       // key tile 0..31
    int kvh = blockIdx.y;
    const float* vb = g_v + ((size_t)kvh * TT + (size_t)j * 64) * HD;
    uint2* dst = g_vs + (size_t)(kvh * 32 + j) * 4096;
    int tid = threadIdx.x;
#pragma unroll
    for (int it = 0; it < 4; it++) {
        int l = tid + it * 256;
        int h4 = l & 31, kp = l >> 5;    // kp: key pair 0..31
        float4 va = *(const float4*)(vb + (size_t)(2 * kp)     * HD + h4 * 4);
        float4 vc = *(const float4*)(vb + (size_t)(2 * kp + 1) * HD + h4 * 4);
        uint2 q0, q1, q2, q3;
        split_pack(va.x, vc.x, q0.x, q0.y);
        split_pack(va.y, vc.y, q1.x, q1.y);
        split_pack(va.z, vc.z, q2.x, q2.y);
        split_pack(va.w, vc.w, q3.x, q3.y);
        dst[(h4 * 4 + 0) * 32 + kp] = q0;
        dst[(h4 * 4 + 1) * 32 + kp] = q1;
        dst[(h4 * 4 + 2) * 32 + kp] = q2;
        dst[(h4 * 4 + 3) * 32 + kp] = q3;
    }
}

// ---------------------------------------------------------------------------
// split-bf16 GEMM core, pure-copy staging (UNCHANGED from R16, known-good).
// ---------------------------------------------------------------------------
#define GS 20   // smem row stride in uint2 (16 used + 4 pad)

template<bool HAS_BIAS>
__device__ __forceinline__ void gemm_core(
    const uint2* __restrict__ Xg,
    const uint2* __restrict__ Wtiles,
    const float* __restrict__ bias,
    float* __restrict__ Obase, int ldo)
{
    __shared__ uint2 Xs[128 * GS];
    __shared__ uint2 Ws[128 * GS];

    int tid  = threadIdx.x;
    int warp = tid >> 5, lane = tid & 31;
    int wm = warp >> 1;
    int wn = warp & 1;
    int g  = lane >> 2;
    int tg = lane & 3;

    float C[2][8][4];
#pragma unroll
    for (int mt = 0; mt < 2; mt++)
#pragma unroll
        for (int nt = 0; nt < 8; nt++)
#pragma unroll
            for (int r = 0; r < 4; r++) C[mt][nt][r] = 0.f;

    for (int kt = 0; kt < KT; kt++) {
#pragma unroll
        for (int it = 0; it < 4; it++) {
            int l = tid + it * 256;
            int row = l >> 3, p = l & 7;
            ((uint4*)&Xs[row * GS])[p] =
                ((const uint4*)&Xg[(size_t)row * (DD / 2) + kt * 16])[p];
        }
        const uint2* wt = Wtiles + (size_t)kt * 2048;
#pragma unroll
        for (int it = 0; it < 4; it++) {
            int l = tid + it * 256;
            int n = l >> 3, p = l & 7;
            ((uint4*)&Ws[n * GS])[p] = ((const uint4*)(wt + n * 16))[p];
        }
        __syncthreads();

#pragma unroll
        for (int kk = 0; kk < 2; kk++) {
            int kpb = kk * 8;
            uint2 A[2][4];
#pragma unroll
            for (int mt = 0; mt < 2; mt++) {
                int r0 = wm * 32 + mt * 16 + g;
                int r1 = r0 + 8;
                A[mt][0] = Xs[r0 * GS + kpb + tg];
                A[mt][1] = Xs[r1 * GS + kpb + tg];
                A[mt][2] = Xs[r0 * GS + kpb + tg + 4];
                A[mt][3] = Xs[r1 * GS + kpb + tg + 4];
            }
#pragma unroll
            for (int nt = 0; nt < 8; nt++) {
                int nb = wn * 64 + nt * 8;
                uint2 b0 = Ws[(nb + g) * GS + kpb + tg];
                uint2 b1 = Ws[(nb + g) * GS + kpb + tg + 4];
                mma3_bf16(C[0][nt], A[0][0], A[0][1], A[0][2], A[0][3], b0, b1);
                mma3_bf16(C[1][nt], A[1][0], A[1][1], A[1][2], A[1][3], b0, b1);
            }
        }
        __syncthreads();
    }

#pragma unroll
    for (int mt = 0; mt < 2; mt++) {
#pragma unroll
        for (int nt = 0; nt < 8; nt++) {
            int row0 = wm * 32 + mt * 16 + g;
            int col  = wn * 64 + nt * 8 + tg * 2;
            float b0v = HAS_BIAS ? bias[col]     : 0.f;
            float b1v = HAS_BIAS ? bias[col + 1] : 0.f;
            *(float2*)&Obase[(size_t)row0 * ldo + col] =
                make_float2(C[mt][nt][0] + b0v, C[mt][nt][1] + b1v);
            *(float2*)&Obase[(size_t)(row0 + 8) * ldo + col] =
                make_float2(C[mt][nt][2] + b0v, C[mt][nt][3] + b1v);
        }
    }
}

__global__ __launch_bounds__(256, 2) void qkv_proj_kernel(
    const float* __restrict__ bq, const float* __restrict__ bk,
    const float* __restrict__ bv)
{
    int z = blockIdx.y;
    const float* b; float* out;
    if (z < NH)           { b = bq + z * HD;              out = g_q + (size_t)z * TT * HD; }
    else if (z < NH + KH) { int c = z - NH;      b = bk + c * HD; out = g_k + (size_t)c * TT * HD; }
    else                  { int c = z - NH - KH; b = bv + c * HD; out = g_v + (size_t)c * TT * HD; }

    int t0 = blockIdx.x * 128;
    gemm_core<true>(g_xs + (size_t)t0 * (DD / 2),
                    g_ws + (size_t)z * KT * 2048,
                    b, out + (size_t)t0 * HD, HD);
}

__global__ __launch_bounds__(256, 2) void out_proj_kernel(float* __restrict__ out)
{
    int t0 = blockIdx.x * 128;
    int nblk = blockIdx.y;
    gemm_core<false>(g_cs + (size_t)t0 * (DD / 2),
                     g_wos + (size_t)nblk * KT * 2048,
                     nullptr, out + (size_t)t0 * DD + nblk * 128, DD);
}

// ---------------------------------------------------------------------------
// Flash attention, split-bf16, pure-copy staging (operands pre-split in gmem).
// Inner MMA/softmax structure identical to R12/R16.
// smem (uint2): Qs[128][68], Ks[64][68], Vs[128][36], Ps[128][36] = 178 KB
// ---------------------------------------------------------------------------
#define FQ_S 68
#define FK_S 68
#define FV_S 36
#define FP_S 36
#define FL_QN (128 * FQ_S)
#define FL_KN (64 * FK_S)
#define FL_VN (128 * FV_S)
#define FL_PN (128 * FP_S)
#define FL_SMEM ((FL_QN + FL_KN + FL_VN + FL_PN) * 8)

__global__ __launch_bounds__(256) void flash_bf16_kernel()
{
    extern __shared__ uint2 smu[];
    uint2* Qs = smu;
    uint2* Ks = Qs + FL_QN;
    uint2* Vs = Ks + FL_KN;
    uint2* Ps = Vs + FL_VN;

    int bq = blockIdx.x;
    int n  = blockIdx.y;
    int kvh = n / GQ;
    int tid = threadIdx.x;
    int warp = tid >> 5, lane = tid & 31;
    int g = lane >> 2, tg = lane & 3;

    // ---- stage Q tile: pure copy, 128 rows x 32 uint4 ----
    const uint2* qsrc = g_qs + ((size_t)n * TT + (size_t)bq * 128) * 64;
#pragma unroll
    for (int it = 0; it < 16; it++) {
        int l = tid + it * 256;
        int row = l >> 5, p = l & 31;
        ((uint4*)&Qs[row * FQ_S])[p] = ((const uint4*)(qsrc + row * 64))[p];
    }

    float O[16][4];
#pragma unroll
    for (int i = 0; i < 16; i++)
#pragma unroll
        for (int r = 0; r < 4; r++) O[i][r] = 0.f;
    float m0 = -1.0e30f, m1 = -1.0e30f, l0 = 0.f, l1 = 0.f;

    int row_loc0 = warp * 16 + g;
    int row_loc1 = row_loc0 + 8;
    int qrow0 = bq * 128 + row_loc0;
    int qrow1 = qrow0 + 8;

    int jmax = 2 * bq + 1;
    for (int j = 0; j <= jmax; j++) {
        __syncthreads();
        // ---- stage K tile: pure copy, 64 rows x 32 uint4 ----
        const uint2* ksrc = g_ks + ((size_t)kvh * TT + (size_t)j * 64) * 64;
#pragma unroll
        for (int it = 0; it < 8; it++) {
            int l = tid + it * 256;
            int row = l >> 5, p = l & 31;
            ((uint4*)&Ks[row * FK_S])[p] = ((const uint4*)(ksrc + row * 64))[p];
        }
        // ---- stage V tile: pure copy, 128 h x 16 uint4 ----
        const uint2* vsrc = g_vs + (size_t)(kvh * 32 + j) * 4096;
#pragma unroll
        for (int it = 0; it < 8; it++) {
            int l = tid + it * 256;
            int h = l >> 4, p = l & 15;
            ((uint4*)&Vs[h * FV_S])[p] = ((const uint4*)(vsrc + h * 32))[p];
        }
        __syncthreads();

        // ---- S = Q K^T (16 rows x 64 cols per warp), 3-MMA bf16 ----
        float c[8][4];
#pragma unroll
        for (int nt = 0; nt < 8; nt++)
#pragma unroll
            for (int r = 0; r < 4; r++) c[nt][r] = 0.f;

#pragma unroll
        for (int kk = 0; kk < 8; kk++) {
            int kpb = kk * 8;
            uint2 a0 = Qs[row_loc0 * FQ_S + kpb + tg];
            uint2 a1 = Qs[row_loc1 * FQ_S + kpb + tg];
            uint2 a2 = Qs[row_loc0 * FQ_S + kpb + tg + 4];
            uint2 a3 = Qs[row_loc1 * FQ_S + kpb + tg + 4];
#pragma unroll
            for (int nt = 0; nt < 8; nt++) {
                uint2 b0 = Ks[(nt * 8 + g) * FK_S + kpb + tg];
                uint2 b1 = Ks[(nt * 8 + g) * FK_S + kpb + tg + 4];
                mma3_bf16(c[nt], a0, a1, a2, a3, b0, b1);
            }
        }

        // ---- causal mask (diagonal tiles only) ----
        if (j >= 2 * bq) {
#pragma unroll
            for (int nt = 0; nt < 8; nt++) {
                int col = j * 64 + nt * 8 + tg * 2;
                if (col     > qrow0) c[nt][0] = -1.0e30f;
                if (col + 1 > qrow0) c[nt][1] = -1.0e30f;
                if (col     > qrow1) c[nt][2] = -1.0e30f;
                if (col + 1 > qrow1) c[nt][3] = -1.0e30f;
            }
        }

        // ---- online softmax (quad-local rows) ----
        float mx0 = -1.0e30f, mx1 = -1.0e30f;
#pragma unroll
        for (int nt = 0; nt < 8; nt++) {
            mx0 = fmaxf(mx0, fmaxf(c[nt][0], c[nt][1]));
            mx1 = fmaxf(mx1, fmaxf(c[nt][2], c[nt][3]));
        }
        mx0 = fmaxf(mx0, __shfl_xor_sync(0xFFFFFFFFu, mx0, 1));
        mx0 = fmaxf(mx0, __shfl_xor_sync(0xFFFFFFFFu, mx0, 2));
        mx1 = fmaxf(mx1, __shfl_xor_sync(0xFFFFFFFFu, mx1, 1));
        mx1 = fmaxf(mx1, __shfl_xor_sync(0xFFFFFFFFu, mx1, 2));

        float mn0 = fmaxf(m0, mx0);
        float mn1 = fmaxf(m1, mx1);
        float al0 = __expf(m0 - mn0);
        float al1 = __expf(m1 - mn1);
        float s0 = 0.f, s1 = 0.f;
#pragma unroll
        for (int nt = 0; nt < 8; nt++) {
            c[nt][0] = __expf(c[nt][0] - mn0);
            c[nt][1] = __expf(c[nt][1] - mn0);
            c[nt][2] = __expf(c[nt][2] - mn1);
            c[nt][3] = __expf(c[nt][3] - mn1);
            s0 += c[nt][0] + c[nt][1];
            s1 += c[nt][2] + c[nt][3];
        }
        s0 += __shfl_xor_sync(0xFFFFFFFFu, s0, 1);
        s0 += __shfl_xor_sync(0xFFFFFFFFu, s0, 2);
        s1 += __shfl_xor_sync(0xFFFFFFFFu, s1, 1);
        s1 += __shfl_xor_sync(0xFFFFFFFFu, s1, 2);

        l0 = l0 * al0 + s0;  m0 = mn0;
        l1 = l1 * al1 + s1;  m1 = mn1;

#pragma unroll
        for (int i = 0; i < 16; i++) {
            O[i][0] *= al0; O[i][1] *= al0;
            O[i][2] *= al1; O[i][3] *= al1;
        }

        // ---- write P pre-split (only remaining on-the-fly split) ----
#pragma unroll
        for (int nt = 0; nt < 8; nt++) {
            uint2 p0, p1;
            split_pack(c[nt][0], c[nt][1], p0.x, p0.y);
            split_pack(c[nt][2], c[nt][3], p1.x, p1.y);
            Ps[row_loc0 * FP_S + nt * 4 + tg] = p0;
            Ps[row_loc1 * FP_S + nt * 4 + tg] = p1;
        }
        __syncwarp();

        // ---- O += P V (16 rows x 128 h per warp), 3-MMA bf16 ----
#pragma unroll
        for (int kk = 0; kk < 4; kk++) {
            int kpb = kk * 8;
            uint2 a0 = Ps[row_loc0 * FP_S + kpb + tg];
            uint2 a1 = Ps[row_loc1 * FP_S + kpb + tg];
            uint2 a2 = Ps[row_loc0 * FP_S + kpb + tg + 4];
            uint2 a3 = Ps[row_loc1 * FP_S + kpb + tg + 4];
#pragma unroll
            for (int nt = 0; nt < 16; nt++) {
                uint2 b0 = Vs[(nt * 8 + g) * FV_S + kpb + tg];
                uint2 b1 = Vs[(nt * 8 + g) * FV_S + kpb + tg + 4];
                mma3_bf16(O[nt], a0, a1, a2, a3, b0, b1);
            }
        }
    }

    // ---- epilogue: divide by l, write ctx[t][n*H + h] ----
    float inv0 = 1.f / l0;
    float inv1 = 1.f / l1;
    int t0 = bq * 128 + row_loc0;
    int t1 = t0 + 8;
#pragma unroll
    for (int nt = 0; nt < 16; nt++) {
        int col = n * HD + nt * 8 + tg * 2;
        *(float2*)&g_ctx[(size_t)t0 * DD + col] = make_float2(O[nt][0] * inv0, O[nt][1] * inv0);
        *(float2*)&g_ctx[(size_t)t1 * DD + col] = make_float2(O[nt][2] * inv1, O[nt][3] * inv1);
    }
}

// ---------------------------------------------------------------------------

extern "C" void kernel_launch(void* const* d_in, const int* in_sizes, int n_in,
                              void* d_out, int out_size)
{
    const float* x         = (const float*)d_in[0];
    const int*   positions = (const int*)d_in[1];
    const float* wq        = (const float*)d_in[2];
    const float* bq        = (const float*)d_in[3];
    const float* wk        = (const float*)d_in[4];
    const float* bk        = (const float*)d_in[5];
    const float* wv        = (const float*)d_in[6];
    const float* bv        = (const float*)d_in[7];
    const float* wo        = (const float*)d_in[8];
    float* out = (float*)d_out;

    presplit_wqkv_kernel<<<dim3(KT, NZ), 512>>>(wq, wk, wv);
    presplit_wo_kernel<<<dim3(KT, DD / 128), 512>>>(wo);
    presplit_x_kernel<<<TT * DD / 4 / 256, 256>>>(x);

    qkv_proj_kernel<<<dim3(TT / 128, NZ), 256>>>(bq, bk, bv);

    rope_split_kernel<<<dim3(TT, NH + KH), 32>>>(positions);
    presplit_v_kernel<<<dim3(32, KH), 256>>>();

    cudaFuncSetAttribute(flash_bf16_kernel, cudaFuncAttributeMaxDynamicSharedMemorySize, FL_SMEM);
    flash_bf16_kernel<<<dim3(TT / 128, NH), 256, FL_SMEM>>>();

    presplit_ctx_kernel<<<TT * DD / 4 / 256, 256>>>();
    out_proj_kernel<<<dim3(TT / 128, DD / 128), 256>>>(out);
}